// round 5
// baseline (speedup 1.0000x reference)
#include <cuda_runtime.h>

#define IMG     512
#define TX      32
#define TY      32
#define KW      11
#define RAD     5
#define HTILE   (TY + KW - 1)   /* 42 */
#define WTILE   (TX + KW - 1)   /* 42 */
#define WPAD    44              /* padded smem row stride in float2 */
#define GX      (IMG / TX)      /* 16 */
#define GY      (IMG / TY)      /* 16 */
#define NPLANES 48
#define NBLK    (GX * GY * NPLANES)  /* 12288 */
#define NPIXD   12582912.0           /* 16*3*512*512 */

// Gaussian window (sigma=1.5, K=11), normalized. Literals -> FFMA-imm.
#define G0  1.0283800e-03f
#define G1  7.5988187e-03f
#define G2  3.6000773e-02f
#define G3  1.0936069e-01f
#define G4  2.1300553e-01f
#define G5  2.6601131e-01f
#define G6  G4
#define G7  G3
#define G8  G2
#define G9  G1
#define G10 G0

// 11-tap conv over expression E(j) for j = i..i+10 (immediate multipliers).
#define CONV11E(E, i)                                                  \
    fmaf(G10, E((i) + 10),                                             \
    fmaf(G9,  E((i) + 9),                                              \
    fmaf(G8,  E((i) + 8),                                              \
    fmaf(G7,  E((i) + 7),                                              \
    fmaf(G6,  E((i) + 6),                                              \
    fmaf(G5,  E((i) + 5),                                              \
    fmaf(G4,  E((i) + 4),                                              \
    fmaf(G3,  E((i) + 3),                                              \
    fmaf(G2,  E((i) + 2),                                              \
    fmaf(G1,  E((i) + 1),                                              \
    G0 * E((i) + 0)))))))))))

__device__ float g_part[NBLK];
__device__ int   g_count = 0;

__global__ __launch_bounds__(256, 4) void ssim_main(const float* __restrict__ x,
                                                    const float* __restrict__ y,
                                                    float* __restrict__ out) {
    __shared__ float2 xys[HTILE][WPAD];        // (x, y) interleaved,   14.8 KB
    __shared__ float2 Hs01[HTILE][TX];         // (hx, hy),             10.5 KB
    __shared__ float2 Hs23[HTILE][TX];         // (hxx, hyy),           10.5 KB
    __shared__ float  Hs4[HTILE][TX];          // hxy,                   5.3 KB
    __shared__ float  red[8];

    const int tid   = threadIdx.x;
    const int plane = blockIdx.z;
    const int c0    = blockIdx.x * TX;
    const int r0    = blockIdx.y * TY;
    const float* xp = x + (size_t)plane * (IMG * IMG);
    const float* yp = y + (size_t)plane * (IMG * IMG);

    // ---- Phase 0: cooperative halo load, interleaved float2 store ----
    for (int i = tid; i < HTILE * WTILE; i += 256) {
        int lr = i / WTILE, lc = i - lr * WTILE;
        int gr = r0 + lr - RAD, gc = c0 + lc - RAD;
        bool ok = (gr >= 0) & (gr < IMG) & (gc >= 0) & (gc < IMG);
        float xv = 0.f, yv = 0.f;
        if (ok) {
            int g = gr * IMG + gc;
            xv = xp[g];
            yv = yp[g];
        }
        xys[lr][lc] = make_float2(xv, yv);
    }
    __syncthreads();

    // ---- Phase 1: horizontal conv, 4-column chunks, minimal live set ----
    // 42 rows * 8 chunks = 336 tasks on 256 threads
    for (int t = tid; t < HTILE * (TX / 4); t += 256) {
        int lr  = t >> 3;
        int cc4 = (t & 7) << 2;   // output col base

        float2 v[14];             // (x, y) pairs; 7 x LDS.128
#pragma unroll
        for (int q = 0; q < 7; q++)
            *(float4*)&v[q * 2] = *(const float4*)&xys[lr][cc4 + q * 2];

        // (hx, hy) pair conv
        float2 h01[4];
#define EX(j) v[j].x
#define EY(j) v[j].y
#pragma unroll
        for (int cc = 0; cc < 4; cc++) {
            h01[cc].x = CONV11E(EX, cc);
            h01[cc].y = CONV11E(EY, cc);
        }
        *(float4*)&Hs01[lr][cc4 + 0] = *(float4*)&h01[0];
        *(float4*)&Hs01[lr][cc4 + 2] = *(float4*)&h01[2];

        // hxy conv, fused product (no scratch array)
        float h4[4];
#define EXY(j) (v[j].x * v[j].y)
#pragma unroll
        for (int cc = 0; cc < 4; cc++) h4[cc] = CONV11E(EXY, cc);
        *(float4*)&Hs4[lr][cc4] = *(float4*)h4;

        // square in place, then (hxx, hyy) pair conv
#pragma unroll
        for (int j = 0; j < 14; j++) {
            v[j].x *= v[j].x;
            v[j].y *= v[j].y;
        }
        float2 h23[4];
#pragma unroll
        for (int cc = 0; cc < 4; cc++) {
            h23[cc].x = CONV11E(EX, cc);
            h23[cc].y = CONV11E(EY, cc);
        }
        *(float4*)&Hs23[lr][cc4 + 0] = *(float4*)&h23[0];
        *(float4*)&Hs23[lr][cc4 + 2] = *(float4*)&h23[2];
#undef EX
#undef EY
#undef EXY
    }
    __syncthreads();

    // ---- Phase 2: vertical conv + SSIM (4-row window per thread) ----
    const int lane = tid & 31;          // output column
    const int wrow = (tid >> 5) << 2;   // warp w -> output rows 4w..4w+3
    const float C1 = 0.0001f, C2 = 0.0009f;

    float mu1[4], mu2[4], cxx[4], cyy[4], cxy[4];
    {
        float2 a[14];                   // 14 x LDS.64
#define AX(j) a[j].x
#define AY(j) a[j].y
#pragma unroll
        for (int j = 0; j < 14; j++) a[j] = Hs01[wrow + j][lane];
#pragma unroll
        for (int i = 0; i < 4; i++) {
            mu1[i] = CONV11E(AX, i);
            mu2[i] = CONV11E(AY, i);
        }
#pragma unroll
        for (int j = 0; j < 14; j++) a[j] = Hs23[wrow + j][lane];
#pragma unroll
        for (int i = 0; i < 4; i++) {
            cxx[i] = CONV11E(AX, i);
            cyy[i] = CONV11E(AY, i);
        }
#undef AX
#undef AY
    }
    {
        float b[14];                    // 14 x LDS.32
#define BB(j) b[j]
#pragma unroll
        for (int j = 0; j < 14; j++) b[j] = Hs4[wrow + j][lane];
#pragma unroll
        for (int i = 0; i < 4; i++) cxy[i] = CONV11E(BB, i);
#undef BB
    }

    float local = 0.f;
#pragma unroll
    for (int i = 0; i < 4; i++) {
        float m1 = mu1[i], m2 = mu2[i];
        float m1s = m1 * m1, m2s = m2 * m2, m12 = m1 * m2;
        float s1  = cxx[i] - m1s;
        float s2  = cyy[i] - m2s;
        float s12 = cxy[i] - m12;
        float num = (2.f * m12 + C1) * (2.f * s12 + C2);
        float den = (m1s + m2s + C1) * (s1 + s2 + C2);
        local += __fdividef(num, den);
    }

    // ---- block reduction ----
#pragma unroll
    for (int o = 16; o; o >>= 1) local += __shfl_down_sync(0xffffffffu, local, o);
    if (lane == 0) red[tid >> 5] = local;
    __syncthreads();

    __shared__ bool amLast;
    if (tid == 0) {
        float s = 0.f;
#pragma unroll
        for (int w = 0; w < 8; w++) s += red[w];
        int bidx = (blockIdx.z * GY + blockIdx.y) * GX + blockIdx.x;
        g_part[bidx] = s;
        __threadfence();
        int prev = atomicAdd(&g_count, 1);
        amLast = (prev == NBLK - 1);
    }
    __syncthreads();

    // ---- last block: deterministic final reduction (fixed-order reads) ----
    if (amLast) {
        __threadfence();
        double s = 0.0;
        for (int i = tid; i < NBLK; i += 256) s += (double)g_part[i];
#pragma unroll
        for (int o = 16; o; o >>= 1) s += __shfl_down_sync(0xffffffffu, s, o);
        __shared__ double dred[8];
        if (lane == 0) dred[tid >> 5] = s;
        __syncthreads();
        if (tid == 0) {
            double tot = 0.0;
#pragma unroll
            for (int w = 0; w < 8; w++) tot += dred[w];
            out[0] = (float)(1.0 - tot / NPIXD);
            g_count = 0;   // reset for next graph replay
        }
    }
}

extern "C" void kernel_launch(void* const* d_in, const int* in_sizes, int n_in,
                              void* d_out, int out_size) {
    const float* pred  = (const float*)d_in[0];
    const float* label = (const float*)d_in[1];
    float* out = (float*)d_out;

    dim3 grid(GX, GY, NPLANES);   // 16 x 16 x 48
    ssim_main<<<grid, 256>>>(pred, label, out);
}

// round 6
// speedup vs baseline: 1.2011x; 1.2011x over previous
#include <cuda_runtime.h>

#define IMG     512
#define TX      32
#define TY      32
#define KW      11
#define RAD     5
#define HTILE   (TY + KW - 1)   /* 42 */
#define WTILE   (TX + KW - 1)   /* 42 */
#define WPAD    44              /* padded smem row stride in float2 */
#define GX      (IMG / TX)      /* 16 */
#define GY      (IMG / TY)      /* 16 */
#define NPLANES 48
#define NBLK    (GX * GY * NPLANES)  /* 12288 */
#define NPIXD   12582912.0           /* 16*3*512*512 */

// Gaussian window (sigma=1.5, K=11), normalized. Literals -> FFMA-imm (rt=1).
#define G0  1.0283800e-03f
#define G1  7.5988187e-03f
#define G2  3.6000773e-02f
#define G3  1.0936069e-01f
#define G4  2.1300553e-01f
#define G5  2.6601131e-01f
#define G6  G4
#define G7  G3
#define G8  G2
#define G9  G1
#define G10 G0

// 11-tap conv over expression E(j), j = i..i+10 (immediate multipliers).
#define CONV11E(E, i)                                                  \
    fmaf(G10, E((i) + 10),                                             \
    fmaf(G9,  E((i) + 9),                                              \
    fmaf(G8,  E((i) + 8),                                              \
    fmaf(G7,  E((i) + 7),                                              \
    fmaf(G6,  E((i) + 6),                                              \
    fmaf(G5,  E((i) + 5),                                              \
    fmaf(G4,  E((i) + 4),                                              \
    fmaf(G3,  E((i) + 3),                                              \
    fmaf(G2,  E((i) + 2),                                              \
    fmaf(G1,  E((i) + 1),                                               \
    G0 * E((i) + 0)))))))))))

__device__ float g_part[NBLK];
__device__ int   g_count = 0;

__global__ __launch_bounds__(256, 4) void ssim_main(const float* __restrict__ x,
                                                    const float* __restrict__ y,
                                                    float* __restrict__ out) {
    // Fields after horizontal conv: (hx, hy) pair and (hz, hw) pair,
    // where z = x^2 + y^2 (conv linearity: conv(x^2)+conv(y^2) = conv(z)),
    // w = x*y.
    __shared__ float2 xys[HTILE][WPAD];        // (x, y) input tile   14.8 KB
    __shared__ float2 Hs01[HTILE][TX];         // (hx, hy)            10.5 KB
    __shared__ float2 Hszw[HTILE][TX];         // (hz, hw)            10.5 KB
    __shared__ float  red[8];

    const int tid   = threadIdx.x;
    const int plane = blockIdx.z;
    const int c0    = blockIdx.x * TX;
    const int r0    = blockIdx.y * TY;
    const float* xp = x + (size_t)plane * (IMG * IMG);
    const float* yp = y + (size_t)plane * (IMG * IMG);

    // ---- Phase 0: cooperative halo load (zero-pad at image borders) ----
    for (int i = tid; i < HTILE * WTILE; i += 256) {
        int lr = i / WTILE, lc = i - lr * WTILE;
        int gr = r0 + lr - RAD, gc = c0 + lc - RAD;
        bool ok = (gr >= 0) & (gr < IMG) & (gc >= 0) & (gc < IMG);
        float xv = 0.f, yv = 0.f;
        if (ok) {
            int g = gr * IMG + gc;
            xv = xp[g];
            yv = yp[g];
        }
        xys[lr][lc] = make_float2(xv, yv);
    }
    __syncthreads();

    // ---- Phase 1: horizontal conv of 4 fields, 4-column chunks ----
    // 42 rows * 8 chunks = 336 tasks on 256 threads
    for (int t = tid; t < HTILE * (TX / 4); t += 256) {
        int lr  = t >> 3;
        int cc4 = (t & 7) << 2;

        float2 v[14];             // (x, y); 7 x LDS.128
#pragma unroll
        for (int q = 0; q < 7; q++)
            *(float4*)&v[q * 2] = *(const float4*)&xys[lr][cc4 + q * 2];

#define EX(j) v[j].x
#define EY(j) v[j].y
        float2 h[4];
#pragma unroll
        for (int cc = 0; cc < 4; cc++) {
            h[cc].x = CONV11E(EX, cc);
            h[cc].y = CONV11E(EY, cc);
        }
        *(float4*)&Hs01[lr][cc4 + 0] = *(float4*)&h[0];
        *(float4*)&Hs01[lr][cc4 + 2] = *(float4*)&h[2];

        // in-place: v[j] := (x^2 + y^2, x*y)
#pragma unroll
        for (int j = 0; j < 14; j++) {
            float a = v[j].x, b = v[j].y;
            v[j].x = fmaf(a, a, b * b);
            v[j].y = a * b;
        }
#pragma unroll
        for (int cc = 0; cc < 4; cc++) {
            h[cc].x = CONV11E(EX, cc);
            h[cc].y = CONV11E(EY, cc);
        }
        *(float4*)&Hszw[lr][cc4 + 0] = *(float4*)&h[0];
        *(float4*)&Hszw[lr][cc4 + 2] = *(float4*)&h[2];
#undef EX
#undef EY
    }
    __syncthreads();

    // ---- Phase 2: vertical conv + SSIM (4-row window per thread) ----
    const int lane = tid & 31;          // output column
    const int wrow = (tid >> 5) << 2;   // warp w -> output rows 4w..4w+3
    const float C1 = 0.0001f, C2 = 0.0009f;

    float A[4], B[4];                   // A = mu1*mu2, B = mu1^2 + mu2^2
    {
        float2 a[14];
#define AX(j) a[j].x
#define AY(j) a[j].y
#pragma unroll
        for (int j = 0; j < 14; j++) a[j] = Hs01[wrow + j][lane];
#pragma unroll
        for (int i = 0; i < 4; i++) {
            float m1 = CONV11E(AX, i);
            float m2 = CONV11E(AY, i);
            A[i] = m1 * m2;
            B[i] = fmaf(m1, m1, m2 * m2);
        }

        float local = 0.f;
#pragma unroll
        for (int j = 0; j < 14; j++) a[j] = Hszw[wrow + j][lane];
#pragma unroll
        for (int i = 0; i < 4; i++) {
            float czz = CONV11E(AX, i);   // conv(x^2)+conv(y^2)
            float cxy = CONV11E(AY, i);   // conv(x*y)
            float num = (2.f * A[i] + C1) * (2.f * (cxy - A[i]) + C2);
            float den = (B[i] + C1) * ((czz - B[i]) + C2);
            local += __fdividef(num, den);
        }
#undef AX
#undef AY

        // ---- block reduction ----
#pragma unroll
        for (int o = 16; o; o >>= 1) local += __shfl_down_sync(0xffffffffu, local, o);
        if (lane == 0) red[tid >> 5] = local;
    }
    __syncthreads();

    __shared__ bool amLast;
    if (tid == 0) {
        float s = 0.f;
#pragma unroll
        for (int w = 0; w < 8; w++) s += red[w];
        int bidx = (blockIdx.z * GY + blockIdx.y) * GX + blockIdx.x;
        g_part[bidx] = s;
        __threadfence();
        int prev = atomicAdd(&g_count, 1);
        amLast = (prev == NBLK - 1);
    }
    __syncthreads();

    // ---- last block: deterministic final reduction (fixed-order reads) ----
    if (amLast) {
        __threadfence();
        double s = 0.0;
        for (int i = tid; i < NBLK; i += 256) s += (double)g_part[i];
#pragma unroll
        for (int o = 16; o; o >>= 1) s += __shfl_down_sync(0xffffffffu, s, o);
        __shared__ double dred[8];
        if (lane == 0) dred[tid >> 5] = s;
        __syncthreads();
        if (tid == 0) {
            double tot = 0.0;
#pragma unroll
            for (int w = 0; w < 8; w++) tot += dred[w];
            out[0] = (float)(1.0 - tot / NPIXD);
            g_count = 0;   // reset for next graph replay
        }
    }
}

extern "C" void kernel_launch(void* const* d_in, const int* in_sizes, int n_in,
                              void* d_out, int out_size) {
    const float* pred  = (const float*)d_in[0];
    const float* label = (const float*)d_in[1];
    float* out = (float*)d_out;

    dim3 grid(GX, GY, NPLANES);   // 16 x 16 x 48
    ssim_main<<<grid, 256>>>(pred, label, out);
}